// round 16
// baseline (speedup 1.0000x reference)
#include <cuda_runtime.h>
#include <cuda_fp16.h>
#include <cstdint>

#define BATCH 8
#define NNODE 2048
#define NEDGE 65536
#define HDIM  128
#define NRAD  6
#define TILE_E 256

typedef unsigned long long u64;

// ---------------- device globals (no allocation) ----------------
// GEMM-2 B fragments (W fp16) + aug node-term tile (kt=8):
//   g_WB[(j*9 + kt)*32 + lane] : low32 = b0, high32 = b1 (b1=0 for kt=8)
__device__ u64 g_WB[16 * 9 * 32];
// GEMM-1 B fragments (rbf_w fp16, bias in channel m=6):
__device__ uint32_t g_RW[16 * 32];

// ---------------- helpers ----------------
__device__ __forceinline__ uint32_t smem_u32(const void* p) {
    uint32_t a;
    asm("{ .reg .u64 t; cvta.to.shared.u64 t, %1; cvt.u32.u64 %0, t; }" : "=r"(a) : "l"(p));
    return a;
}
__device__ __forceinline__ uint32_t cvt_f16x2(float lo, float hi) {
    uint32_t d;
    asm("cvt.rn.f16x2.f32 %0, %2, %1;" : "=r"(d) : "f"(lo), "f"(hi));
    return d;
}
__device__ __forceinline__ void mma16816(float* d, uint32_t a0, uint32_t a1,
                                         uint32_t a2, uint32_t a3,
                                         uint32_t b0, uint32_t b1) {
    asm volatile(
        "mma.sync.aligned.m16n8k16.row.col.f32.f16.f16.f32 "
        "{%0,%1,%2,%3}, {%4,%5,%6,%7}, {%8,%9}, {%0,%1,%2,%3};"
        : "+f"(d[0]), "+f"(d[1]), "+f"(d[2]), "+f"(d[3])
        : "r"(a0), "r"(a1), "r"(a2), "r"(a3), "r"(b0), "r"(b1));
}
__device__ __forceinline__ void sts64(uint32_t addr, float a, float b) {
    asm volatile("st.shared.v2.f32 [%0], {%1,%2};" :: "r"(addr), "f"(a), "f"(b) : "memory");
}
__device__ __forceinline__ float4 lds128f(uint32_t addr) {
    float4 v;
    asm volatile("ld.shared.v4.f32 {%0,%1,%2,%3}, [%4];"
                 : "=f"(v.x), "=f"(v.y), "=f"(v.z), "=f"(v.w) : "r"(addr));
    return v;
}
// silu via single-MUFU tanh
__device__ __forceinline__ float silu_t(float z) {
    float h = 0.5f * z;
    float t;
    asm("tanh.approx.f32 %0, %1;" : "=f"(t) : "f"(h));
    return fmaf(h, t, h);
}
__device__ __forceinline__ float h16(float v) {
    return __half2float(__float2half_rn(v));
}
// aug A fragment: channels by q: 0:(xih,xih) 1:(xil,xjh) 2:(xjh,xjl) 3:(1,1)
__device__ __forceinline__ uint32_t aug_frag(float xi, float xj, int q) {
    if (q == 0) return cvt_f16x2(xi, xi);
    if (q == 1) return cvt_f16x2(xi - h16(xi), xj);
    if (q == 2) return cvt_f16x2(xj, xj - h16(xj));
    return 0x3C003C00u;
}

// ---------------------------------------------------------------------------
// Single precompute kernel, grid=26, block=256 (2 launches/replay).
// ---------------------------------------------------------------------------
__global__ void precompute_all(const float* __restrict__ emb_w,
                               const float* __restrict__ emb_b,
                               const float* __restrict__ rbf_w,
                               const float* __restrict__ rbf_b,
                               const float* __restrict__ lin_w,
                               const float* __restrict__ lin_b) {
    const int tid = threadIdx.x;
    const int bid = blockIdx.x;

    if (bid < 16) {
        const int idx  = bid * 256 + tid;        // 0..4095
        const int lane = idx & 31;
        const int t    = idx >> 5;               // 0..127
        const int kt   = t & 7;
        const int j    = t >> 3;
        const int o  = j * 8 + (lane >> 2);
        const int k0 = kt * 16 + (lane & 3) * 2;
        const float* wrow = lin_w + o * (3 * HDIM) + 2 * HDIM;
        uint32_t b0 = cvt_f16x2(wrow[k0],     wrow[k0 + 1]);
        uint32_t b1 = cvt_f16x2(wrow[k0 + 8], wrow[k0 + 9]);
        g_WB[(j * 9 + kt) * 32 + lane] = (u64)b0 | ((u64)b1 << 32);
    } else if (bid < 24) {
        const int t = bid - 16;                  // o block [16t, 16t+16)
        __shared__ float su[16][3];
        const int w    = tid >> 5;
        const int lane = tid & 31;
        #pragma unroll
        for (int r = 0; r < 2; ++r) {
            const int o = t * 16 + w * 2 + r;
            const float* row = lin_w + o * (3 * HDIM);
            float u1 = 0.f, u2 = 0.f, cc = 0.f;
            #pragma unroll
            for (int s = 0; s < 4; ++s) {
                const int h = lane + s * 32;
                float w1 = row[h], w2 = row[HDIM + h];
                float ew = emb_w[h], eb = emb_b[h];
                u1 = fmaf(w1, ew, u1);
                u2 = fmaf(w2, ew, u2);
                cc = fmaf(w1 + w2, eb, cc);
            }
            #pragma unroll
            for (int s = 16; s > 0; s >>= 1) {
                u1 += __shfl_down_sync(0xffffffff, u1, s);
                u2 += __shfl_down_sync(0xffffffff, u2, s);
                cc += __shfl_down_sync(0xffffffff, cc, s);
            }
            if (lane == 0) {
                su[w * 2 + r][0] = u1;
                su[w * 2 + r][1] = u2;
                su[w * 2 + r][2] = cc + lin_b[o];
            }
        }
        __syncthreads();
        if (tid < 64) {
            const int lane2 = tid & 31;
            const int j  = t * 2 + (tid >> 5);
            const int ol = (j * 8 + (lane2 >> 2)) - t * 16;   // 0..15
            const int q  = lane2 & 3;
            float u1 = su[ol][0], u2 = su[ol][1], cc = su[ol][2];
            float u1h = h16(u1), u2h = h16(u2), chf = h16(cc);
            float u1l = u1 - u1h, u2l = u2 - u2h, clf = cc - chf;
            uint32_t b0;
            if      (q == 0) b0 = cvt_f16x2(u1h, u1l);
            else if (q == 1) b0 = cvt_f16x2(u1h, u2h);
            else if (q == 2) b0 = cvt_f16x2(u2l, u2h);
            else             b0 = cvt_f16x2(chf, clf);
            g_WB[(j * 9 + 8) * 32 + lane2] = (u64)b0;
        }
    } else {
        const int idx = (bid - 24) * 256 + tid;  // 0..511
        if (idx < 16 * 32) {
            const int lane = idx & 31;
            const int j = idx >> 5;
            const int n = j * 8 + (lane >> 2);
            const int q = lane & 3;
            float f0, f1;
            if (q == 3) { f0 = rbf_b[n]; f1 = 0.f; }
            else        { f0 = rbf_w[n * NRAD + q * 2]; f1 = rbf_w[n * NRAD + q * 2 + 1]; }
            g_RW[idx] = cvt_f16x2(f0, f1);
        }
    }
}

// Stage buffer: per warp 32 rows x 40 floats (32 data + 8 pad -> 8-bank row shift)
#define SROW 40
#define WSTAGE (32 * SROW)     // 1280 floats/warp; 8 warps = 40960 B

// ---------------------------------------------------------------------------
// Main fused kernel: each warp owns 32 edges (two 16-edge MMA groups A/B);
// W fragments amortized over both groups; epilogue staged per 32-o j-block
// through warp-private smem -> coalesced STG.128. No block barriers.
// ---------------------------------------------------------------------------
__global__ void __launch_bounds__(256, 2)
edge_mlp_kernel(const float* __restrict__ x,
                const float* __restrict__ rbf,
                const int* __restrict__ iidx,
                const int* __restrict__ jidx,
                float* __restrict__ out) {
    __shared__ float stage[8 * WSTAGE];

    const int b    = blockIdx.y;
    const int e0   = blockIdx.x * TILE_E;
    const int tid  = threadIdx.x;
    const int wid  = tid >> 5;
    const int lane = tid & 31;
    const int q    = lane & 3;
    const int r    = lane >> 2;

    const uint32_t ws = smem_u32(stage) + (uint32_t)(wid * WSTAGE * 4);

    // group A edges: eA, eA+8; group B: eA+16, eA+24
    const int eA = e0 + wid * 32 + r;

    // ---- GEMM-1 A fragments for both groups ----
    uint32_t aA0, aA1, aB0, aB1;
    if (q == 3) {
        aA0 = aA1 = aB0 = aB1 = 0x00003C00u;   // bias channel (1.0, 0.0)
    } else {
        const int m0 = q * 2;
        const float2 r0 = *(const float2*)(rbf + ((size_t)b * NEDGE + eA)      * NRAD + m0);
        const float2 r1 = *(const float2*)(rbf + ((size_t)b * NEDGE + eA + 8)  * NRAD + m0);
        const float2 r2 = *(const float2*)(rbf + ((size_t)b * NEDGE + eA + 16) * NRAD + m0);
        const float2 r3 = *(const float2*)(rbf + ((size_t)b * NEDGE + eA + 24) * NRAD + m0);
        aA0 = cvt_f16x2(r0.x, r0.y);
        aA1 = cvt_f16x2(r1.x, r1.y);
        aB0 = cvt_f16x2(r2.x, r2.y);
        aB1 = cvt_f16x2(r3.x, r3.y);
    }

    // ---- aug A fragments (node terms; int32 indices, masked) ----
    uint32_t axA0, axA1, axB0, axB1;
    #pragma unroll
    for (int g = 0; g < 4; ++g) {
        const int e = eA + g * 8;
        int ii = iidx[e] & (NNODE - 1), jj = jidx[e] & (NNODE - 1);
        float xi = x[b * NNODE + ii], xj = x[b * NNODE + jj];
        uint32_t f = aug_frag(xi, xj, q);
        if      (g == 0) axA0 = f;
        else if (g == 1) axA1 = f;
        else if (g == 2) axB0 = f;
        else             axB1 = f;
    }

    // ---- streaming GEMM-1 + silu + cvt -> A2 for both groups ----
    uint32_t A2a[8][4], A2b[8][4];
    #pragma unroll
    for (int kt = 0; kt < 8; ++kt) {
        uint32_t w0 = __ldg(g_RW + (2 * kt + 0) * 32 + lane);
        uint32_t w1 = __ldg(g_RW + (2 * kt + 1) * 32 + lane);
        float zA0[4] = {0,0,0,0}, zA1[4] = {0,0,0,0};
        float zB0[4] = {0,0,0,0}, zB1[4] = {0,0,0,0};
        mma16816(zA0, aA0, aA1, 0u, 0u, w0, 0u);
        mma16816(zA1, aA0, aA1, 0u, 0u, w1, 0u);
        mma16816(zB0, aB0, aB1, 0u, 0u, w0, 0u);
        mma16816(zB1, aB0, aB1, 0u, 0u, w1, 0u);
        A2a[kt][0] = cvt_f16x2(silu_t(zA0[0]), silu_t(zA0[1]));
        A2a[kt][1] = cvt_f16x2(silu_t(zA0[2]), silu_t(zA0[3]));
        A2a[kt][2] = cvt_f16x2(silu_t(zA1[0]), silu_t(zA1[1]));
        A2a[kt][3] = cvt_f16x2(silu_t(zA1[2]), silu_t(zA1[3]));
        A2b[kt][0] = cvt_f16x2(silu_t(zB0[0]), silu_t(zB0[1]));
        A2b[kt][1] = cvt_f16x2(silu_t(zB0[2]), silu_t(zB0[3]));
        A2b[kt][2] = cvt_f16x2(silu_t(zB1[0]), silu_t(zB1[1]));
        A2b[kt][3] = cvt_f16x2(silu_t(zB1[2]), silu_t(zB1[3]));
    }

    // ---- GEMM-2 in 4 j-blocks of 4 (32 o each); staged coalesced epilogue ----
    const size_t outRow0 = ((size_t)b * NEDGE + (size_t)(e0 + wid * 32)) * HDIM;

    #pragma unroll
    for (int jb = 0; jb < 4; ++jb) {
        float acc[2][4][4];
        #pragma unroll
        for (int g = 0; g < 2; ++g)
            #pragma unroll
            for (int j = 0; j < 4; ++j)
                #pragma unroll
                for (int c = 0; c < 4; ++c) acc[g][j][c] = 0.f;

        #pragma unroll
        for (int kt = 0; kt < 8; ++kt) {
            #pragma unroll
            for (int j = 0; j < 4; ++j) {
                const int jj = jb * 4 + j;
                u64 wv = __ldg(g_WB + (jj * 9 + kt) * 32 + lane);
                uint32_t b0 = (uint32_t)wv, b1 = (uint32_t)(wv >> 32);
                mma16816(acc[0][j], A2a[kt][0], A2a[kt][1], A2a[kt][2], A2a[kt][3], b0, b1);
                mma16816(acc[1][j], A2b[kt][0], A2b[kt][1], A2b[kt][2], A2b[kt][3], b0, b1);
            }
        }
        #pragma unroll
        for (int j = 0; j < 4; ++j) {
            const int jj = jb * 4 + j;
            uint32_t av0 = (uint32_t)__ldg(g_WB + (jj * 9 + 8) * 32 + lane);
            mma16816(acc[0][j], axA0, axA1, 0u, 0u, av0, 0u);
            mma16816(acc[1][j], axB0, axB1, 0u, 0u, av0, 0u);
        }

        __syncwarp();   // WAR: previous jb's readback done before re-staging
        #pragma unroll
        for (int g = 0; g < 2; ++g) {
            #pragma unroll
            for (int j = 0; j < 4; ++j) {
                const uint32_t off = (uint32_t)((j * 8 + q * 2) * 4);
                const uint32_t row0 = (uint32_t)(g * 16 + r);
                sts64(ws + (row0 * SROW) * 4 + off,
                      silu_t(acc[g][j][0]), silu_t(acc[g][j][1]));
                sts64(ws + ((row0 + 8) * SROW) * 4 + off,
                      silu_t(acc[g][j][2]), silu_t(acc[g][j][3]));
            }
        }
        __syncwarp();   // RAW: staging visible

        // readback: 4 rows per instruction (row = u*4 + lane>>3), 16B/lane
        const int rw = lane >> 3;           // 0..3
        const int cb = (lane & 7) * 4;      // float offset within 32-float row
        #pragma unroll
        for (int u = 0; u < 8; ++u) {
            const int row = u * 4 + rw;     // 0..31 == edge offset in warp
            float4 v = lds128f(ws + (uint32_t)((row * SROW + cb) * 4));
            *(float4*)(out + outRow0 + (size_t)row * HDIM + jb * 32 + cb) = v;
        }
    }
}

// ---------------------------------------------------------------------------
extern "C" void kernel_launch(void* const* d_in, const int* in_sizes, int n_in,
                              void* d_out, int out_size) {
    const float* x     = (const float*)d_in[0];
    const float* rbf   = (const float*)d_in[1];
    const int*   iidx  = (const int*)d_in[2];   // int32 (JAX x64 disabled)
    const int*   jidx  = (const int*)d_in[3];
    const float* emb_w = (const float*)d_in[4];
    const float* emb_b = (const float*)d_in[5];
    const float* rbf_w = (const float*)d_in[6];
    const float* rbf_b = (const float*)d_in[7];
    const float* lin_w = (const float*)d_in[8];
    const float* lin_b = (const float*)d_in[9];
    float* out = (float*)d_out;

    precompute_all<<<26, 256>>>(emb_w, emb_b, rbf_w, rbf_b, lin_w, lin_b);

    dim3 grid(NEDGE / TILE_E, BATCH);   // (256, 8)
    edge_mlp_kernel<<<grid, 256>>>(x, rbf, iidx, jidx, out);
}

// round 17
// speedup vs baseline: 1.0589x; 1.0589x over previous
#include <cuda_runtime.h>
#include <cuda_fp16.h>
#include <cstdint>

#define BATCH 8
#define NNODE 2048
#define NEDGE 65536
#define HDIM  128
#define NRAD  6
#define TILE_E 128

typedef unsigned long long u64;

// ---------------- device globals (no allocation) ----------------
// GEMM-2 B fragments (W fp16) + aug node-term tile (kt=8):
//   g_WB[(j*9 + kt)*32 + lane] : low32 = b0, high32 = b1 (b1=0 for kt=8)
__device__ u64 g_WB[16 * 9 * 32];
// GEMM-1 B fragments (rbf_w fp16, bias in channel m=6):
__device__ uint32_t g_RW[16 * 32];

// ---------------- helpers ----------------
__device__ __forceinline__ uint32_t smem_u32(const void* p) {
    uint32_t a;
    asm("{ .reg .u64 t; cvta.to.shared.u64 t, %1; cvt.u32.u64 %0, t; }" : "=r"(a) : "l"(p));
    return a;
}
__device__ __forceinline__ uint32_t cvt_f16x2(float lo, float hi) {
    uint32_t d;
    asm("cvt.rn.f16x2.f32 %0, %2, %1;" : "=r"(d) : "f"(lo), "f"(hi));
    return d;
}
__device__ __forceinline__ void mma16816(float* d, uint32_t a0, uint32_t a1,
                                         uint32_t a2, uint32_t a3,
                                         uint32_t b0, uint32_t b1) {
    asm volatile(
        "mma.sync.aligned.m16n8k16.row.col.f32.f16.f16.f32 "
        "{%0,%1,%2,%3}, {%4,%5,%6,%7}, {%8,%9}, {%0,%1,%2,%3};"
        : "+f"(d[0]), "+f"(d[1]), "+f"(d[2]), "+f"(d[3])
        : "r"(a0), "r"(a1), "r"(a2), "r"(a3), "r"(b0), "r"(b1));
}
__device__ __forceinline__ void sts64(uint32_t addr, float a, float b) {
    asm volatile("st.shared.v2.f32 [%0], {%1,%2};" :: "r"(addr), "f"(a), "f"(b) : "memory");
}
__device__ __forceinline__ float4 lds128f(uint32_t addr) {
    float4 v;
    asm volatile("ld.shared.v4.f32 {%0,%1,%2,%3}, [%4];"
                 : "=f"(v.x), "=f"(v.y), "=f"(v.z), "=f"(v.w) : "r"(addr));
    return v;
}
// silu via single-MUFU tanh
__device__ __forceinline__ float silu_t(float z) {
    float h = 0.5f * z;
    float t;
    asm("tanh.approx.f32 %0, %1;" : "=f"(t) : "f"(h));
    return fmaf(h, t, h);
}
__device__ __forceinline__ float h16(float v) {
    return __half2float(__float2half_rn(v));
}
// aug A fragment: channels by q: 0:(xih,xih) 1:(xil,xjh) 2:(xjh,xjl) 3:(1,1)
__device__ __forceinline__ uint32_t aug_frag(float xi, float xj, int q) {
    if (q == 0) return cvt_f16x2(xi, xi);
    if (q == 1) return cvt_f16x2(xi - h16(xi), xj);
    if (q == 2) return cvt_f16x2(xj, xj - h16(xj));
    return 0x3C003C00u;
}

// ---------------------------------------------------------------------------
// Single precompute kernel, grid=26, block=256 (2 launches/replay).
// ---------------------------------------------------------------------------
__global__ void precompute_all(const float* __restrict__ emb_w,
                               const float* __restrict__ emb_b,
                               const float* __restrict__ rbf_w,
                               const float* __restrict__ rbf_b,
                               const float* __restrict__ lin_w,
                               const float* __restrict__ lin_b) {
    const int tid = threadIdx.x;
    const int bid = blockIdx.x;

    if (bid < 16) {
        const int idx  = bid * 256 + tid;        // 0..4095
        const int lane = idx & 31;
        const int t    = idx >> 5;               // 0..127
        const int kt   = t & 7;
        const int j    = t >> 3;
        const int o  = j * 8 + (lane >> 2);
        const int k0 = kt * 16 + (lane & 3) * 2;
        const float* wrow = lin_w + o * (3 * HDIM) + 2 * HDIM;
        uint32_t b0 = cvt_f16x2(wrow[k0],     wrow[k0 + 1]);
        uint32_t b1 = cvt_f16x2(wrow[k0 + 8], wrow[k0 + 9]);
        g_WB[(j * 9 + kt) * 32 + lane] = (u64)b0 | ((u64)b1 << 32);
    } else if (bid < 24) {
        const int t = bid - 16;                  // o block [16t, 16t+16)
        __shared__ float su[16][3];
        const int w    = tid >> 5;
        const int lane = tid & 31;
        #pragma unroll
        for (int r = 0; r < 2; ++r) {
            const int o = t * 16 + w * 2 + r;
            const float* row = lin_w + o * (3 * HDIM);
            float u1 = 0.f, u2 = 0.f, cc = 0.f;
            #pragma unroll
            for (int s = 0; s < 4; ++s) {
                const int h = lane + s * 32;
                float w1 = row[h], w2 = row[HDIM + h];
                float ew = emb_w[h], eb = emb_b[h];
                u1 = fmaf(w1, ew, u1);
                u2 = fmaf(w2, ew, u2);
                cc = fmaf(w1 + w2, eb, cc);
            }
            #pragma unroll
            for (int s = 16; s > 0; s >>= 1) {
                u1 += __shfl_down_sync(0xffffffff, u1, s);
                u2 += __shfl_down_sync(0xffffffff, u2, s);
                cc += __shfl_down_sync(0xffffffff, cc, s);
            }
            if (lane == 0) {
                su[w * 2 + r][0] = u1;
                su[w * 2 + r][1] = u2;
                su[w * 2 + r][2] = cc + lin_b[o];
            }
        }
        __syncthreads();
        if (tid < 64) {
            const int lane2 = tid & 31;
            const int j  = t * 2 + (tid >> 5);
            const int ol = (j * 8 + (lane2 >> 2)) - t * 16;   // 0..15
            const int q  = lane2 & 3;
            float u1 = su[ol][0], u2 = su[ol][1], cc = su[ol][2];
            float u1h = h16(u1), u2h = h16(u2), chf = h16(cc);
            float u1l = u1 - u1h, u2l = u2 - u2h, clf = cc - chf;
            uint32_t b0;
            if      (q == 0) b0 = cvt_f16x2(u1h, u1l);
            else if (q == 1) b0 = cvt_f16x2(u1h, u2h);
            else if (q == 2) b0 = cvt_f16x2(u2l, u2h);
            else             b0 = cvt_f16x2(chf, clf);
            g_WB[(j * 9 + 8) * 32 + lane2] = (u64)b0;
        }
    } else {
        const int idx = (bid - 24) * 256 + tid;  // 0..511
        if (idx < 16 * 32) {
            const int lane = idx & 31;
            const int j = idx >> 5;
            const int n = j * 8 + (lane >> 2);
            const int q = lane & 3;
            float f0, f1;
            if (q == 3) { f0 = rbf_b[n]; f1 = 0.f; }
            else        { f0 = rbf_w[n * NRAD + q * 2]; f1 = rbf_w[n * NRAD + q * 2 + 1]; }
            g_RW[idx] = cvt_f16x2(f0, f1);
        }
    }
}

// Epilogue stage buffer: per warp, 16 rows x 68 floats (64 data + 4 pad).
#define SROW 68                       // floats per staged half-row
#define WSTAGE (16 * SROW)            // 1088 floats per warp
// 8 warps * 1088 * 4B = 34816 B static shared; 3 CTAs/SM = 104 KB (fits)

// ---------------------------------------------------------------------------
// Main fused kernel (R15 structure at 3 CTAs/SM): barrier-free between warps;
// each warp owns 16 edges; stores restaged through warp-private smem ->
// coalesced STG.128.
// ---------------------------------------------------------------------------
__global__ void __launch_bounds__(256, 3)
edge_mlp_kernel(const float* __restrict__ x,
                const float* __restrict__ rbf,
                const int* __restrict__ iidx,
                const int* __restrict__ jidx,
                float* __restrict__ out) {
    __shared__ float stage[8 * WSTAGE];

    const int b    = blockIdx.y;
    const int e0   = blockIdx.x * TILE_E;
    const int tid  = threadIdx.x;
    const int wid  = tid >> 5;
    const int lane = tid & 31;
    const int q    = lane & 3;
    const int r    = lane >> 2;

    const uint32_t wstage = smem_u32(stage) + (uint32_t)(wid * WSTAGE * 4);

    const int e_lo = e0 + wid * 16 + r;
    const int e_hi = e_lo + 8;

    // ---- GEMM-1 A fragments: rbf channels (m0, m0+1); q==3 -> bias ch (1,0)
    uint32_t a0, a1;
    if (q == 3) {
        a0 = a1 = 0x00003C00u;     // (1.0, 0.0)
    } else {
        const int m0 = q * 2;
        const float2 rl = *(const float2*)(rbf + ((size_t)b * NEDGE + e_lo) * NRAD + m0);
        const float2 rh = *(const float2*)(rbf + ((size_t)b * NEDGE + e_hi) * NRAD + m0);
        a0 = cvt_f16x2(rl.x, rl.y);
        a1 = cvt_f16x2(rh.x, rh.y);
    }

    // ---- aug A fragments (node terms; int32 indices, masked) ----
    uint32_t ax0, ax1;
    {
        int il = iidx[e_lo] & (NNODE - 1), jl = jidx[e_lo] & (NNODE - 1);
        int ih = iidx[e_hi] & (NNODE - 1), jh = jidx[e_hi] & (NNODE - 1);
        float xiL = x[b * NNODE + il], xjL = x[b * NNODE + jl];
        float xiH = x[b * NNODE + ih], xjH = x[b * NNODE + jh];
        ax0 = aug_frag(xiL, xjL, q);
        ax1 = aug_frag(xiH, xjH, q);
    }

    // ---- streaming GEMM-1 + silu + cvt -> A2 ----
    uint32_t A2[8][4];
    #pragma unroll
    for (int kt = 0; kt < 8; ++kt) {
        float z0[4] = {0.f, 0.f, 0.f, 0.f};
        float z1[4] = {0.f, 0.f, 0.f, 0.f};
        uint32_t w0 = __ldg(g_RW + (2 * kt + 0) * 32 + lane);
        uint32_t w1 = __ldg(g_RW + (2 * kt + 1) * 32 + lane);
        mma16816(z0, a0, a1, 0u, 0u, w0, 0u);
        mma16816(z1, a0, a1, 0u, 0u, w1, 0u);
        A2[kt][0] = cvt_f16x2(silu_t(z0[0]), silu_t(z0[1]));
        A2[kt][1] = cvt_f16x2(silu_t(z0[2]), silu_t(z0[3]));
        A2[kt][2] = cvt_f16x2(silu_t(z1[0]), silu_t(z1[1]));
        A2[kt][3] = cvt_f16x2(silu_t(z1[2]), silu_t(z1[3]));
    }

    // ---- GEMM-2 in two o-halves + restaged coalesced epilogue ----
    const size_t rowBase = ((size_t)b * NEDGE + (size_t)(e0 + wid * 16)) * HDIM;

    #pragma unroll
    for (int half = 0; half < 2; ++half) {
        float acc[8][4];
        #pragma unroll
        for (int j = 0; j < 8; ++j)
            #pragma unroll
            for (int c = 0; c < 4; ++c) acc[j][c] = 0.f;

        #pragma unroll
        for (int kt = 0; kt < 8; ++kt) {
            #pragma unroll
            for (int j = 0; j < 8; ++j) {
                const int jj = half * 8 + j;
                u64 wv = __ldg(g_WB + (jj * 9 + kt) * 32 + lane);
                mma16816(acc[j], A2[kt][0], A2[kt][1], A2[kt][2], A2[kt][3],
                         (uint32_t)wv, (uint32_t)(wv >> 32));
            }
        }

        __syncwarp();   // WAR: previous half's readback done before re-staging
        #pragma unroll
        for (int j = 0; j < 8; ++j) {
            const int jj = half * 8 + j;
            u64 av = __ldg(g_WB + (jj * 9 + 8) * 32 + lane);
            mma16816(acc[j], ax0, ax1, 0u, 0u, (uint32_t)av, 0u);

            // stage silu'd results: row r (c0,c1) and row r+8 (c2,c3)
            const uint32_t off = (uint32_t)((j * 8 + q * 2) * 4);
            sts64(wstage + (uint32_t)(r * SROW * 4) + off,
                  silu_t(acc[j][0]), silu_t(acc[j][1]));
            sts64(wstage + (uint32_t)((r + 8) * SROW * 4) + off,
                  silu_t(acc[j][2]), silu_t(acc[j][3]));
        }
        __syncwarp();   // RAW: staging visible to all lanes

        // readback: 2 rows per instruction (row = t*2 + lane>>4), 16B/lane
        const int rr  = lane >> 4;          // 0 or 1
        const int cb  = (lane & 15) * 4;    // float offset within 64-float half-row
        #pragma unroll
        for (int t = 0; t < 8; ++t) {
            const int row = t * 2 + rr;
            float4 v = lds128f(wstage + (uint32_t)((row * SROW + cb) * 4));
            *(float4*)(out + rowBase + (size_t)row * HDIM + half * 64 + cb) = v;
        }
    }
}

// ---------------------------------------------------------------------------
extern "C" void kernel_launch(void* const* d_in, const int* in_sizes, int n_in,
                              void* d_out, int out_size) {
    const float* x     = (const float*)d_in[0];
    const float* rbf   = (const float*)d_in[1];
    const int*   iidx  = (const int*)d_in[2];   // int32 (JAX x64 disabled)
    const int*   jidx  = (const int*)d_in[3];
    const float* emb_w = (const float*)d_in[4];
    const float* emb_b = (const float*)d_in[5];
    const float* rbf_w = (const float*)d_in[6];
    const float* rbf_b = (const float*)d_in[7];
    const float* lin_w = (const float*)d_in[8];
    const float* lin_b = (const float*)d_in[9];
    float* out = (float*)d_out;

    precompute_all<<<26, 256>>>(emb_w, emb_b, rbf_w, rbf_b, lin_w, lin_b);

    dim3 grid(NEDGE / TILE_E, BATCH);   // (512, 8)
    edge_mlp_kernel<<<grid, 256>>>(x, rbf, iidx, jidx, out);
}